// round 4
// baseline (speedup 1.0000x reference)
#include <cuda_runtime.h>

#define Bv 32
#define Tv 1000
#define DINv 64
#define Hv 1024

#define NBG 4
#define NJG 32
#define BTILE 8
#define JTILE 32
#define NTHREADS 256
#define NWARPS 8
#define KSLICE (Hv / NWARPS)   // 128

#define WS_STRIDE 32           // floats per k-row of W tile (LDS.128 aligned, conflict-free)
#define HD_STRIDE 10           // float2 per k-row of duplicated h tile (16B aligned)
#define RED_JS 34

#define GRID (NBG * NJG)       // 128 CTAs, 1/SM, all co-resident

// 4 per-group arrival counters, 256B apart (distinct LTS lines)
__device__ unsigned int g_bar[4 * 64];
// ping-pong h state: h_buf[t&1][b][j]
__device__ float h_buf[2][Bv][Hv];

struct Smem {
    float  Ws[Hv * WS_STRIDE];                // 131072 B : W slice [k][j]
    float2 hd[Hv * HD_STRIDE];                //  81920 B : h(t-1) duplicated [k][b] = (v,v)
    float  red[NWARPS][BTILE][RED_JS];        //   8704 B : k-split partials
};
// total = 221696 B < 232448 B

// ---------------------------------------------------------------------------
// Phase 1: u_in = x @ W_in^T + b  -> out ; also resets the step counters.
// ---------------------------------------------------------------------------
__global__ void __launch_bounds__(256)
esn_uin_kernel(const float* __restrict__ x, const float* __restrict__ Wiw,
               const float* __restrict__ Wib, float* __restrict__ out)
{
    if (blockIdx.x == 0 && threadIdx.x < 4) g_bar[threadIdx.x * 64] = 0u;

    __shared__ float2 xs2[DINv * 18];
    __shared__ float  wis[DINv * 130];

    const int tid = threadIdx.x;
    const int R0  = blockIdx.x * 16;

    {
        const int kk = tid & 63, r4 = tid >> 6;
        #pragma unroll
        for (int i = 0; i < 4; ++i) {
            int r = r4 * 4 + i;
            float v = x[(size_t)(R0 + r) * DINv + kk];
            xs2[kk * 18 + r] = make_float2(v, v);
        }
    }

    const int jp = tid & 63;
    const int rq = tid >> 6;
    const unsigned wis_s = (unsigned)__cvta_generic_to_shared(wis);
    const unsigned xs_s  = (unsigned)__cvta_generic_to_shared(xs2);

    for (int jc = 0; jc < 8; ++jc) {
        __syncthreads();
        for (int idx = tid; idx < 128 * DINv; idx += 256) {
            int jj = idx >> 6, kk = idx & 63;
            wis[kk * 130 + jj] = Wiw[(jc * 128 + jj) * DINv + kk];
        }
        __syncthreads();

        float2 bias2 = *(const float2*)&Wib[jc * 128 + 2 * jp];
        unsigned long long acc[4], b2;
        asm("mov.b64 %0,{%1,%2};" : "=l"(b2) : "f"(bias2.x), "f"(bias2.y));
        #pragma unroll
        for (int r = 0; r < 4; ++r) acc[r] = b2;

        unsigned wa = wis_s + (2 * jp) * 4;
        unsigned xa = xs_s + (rq * 4) * 8;
        #pragma unroll 8
        for (int k = 0; k < DINv; ++k) {
            unsigned long long w01, x0, x1, x2, x3;
            asm("ld.shared.u64 %0,[%1];" : "=l"(w01) : "r"(wa));
            asm("ld.shared.u64 %0,[%1];" : "=l"(x0) : "r"(xa));
            asm("ld.shared.u64 %0,[%1+8];" : "=l"(x1) : "r"(xa));
            asm("ld.shared.u64 %0,[%1+16];" : "=l"(x2) : "r"(xa));
            asm("ld.shared.u64 %0,[%1+24];" : "=l"(x3) : "r"(xa));
            asm("fma.rn.f32x2 %0,%1,%2,%0;" : "+l"(acc[0]) : "l"(w01), "l"(x0));
            asm("fma.rn.f32x2 %0,%1,%2,%0;" : "+l"(acc[1]) : "l"(w01), "l"(x1));
            asm("fma.rn.f32x2 %0,%1,%2,%0;" : "+l"(acc[2]) : "l"(w01), "l"(x2));
            asm("fma.rn.f32x2 %0,%1,%2,%0;" : "+l"(acc[3]) : "l"(w01), "l"(x3));
            wa += 130 * 4;
            xa += 18 * 8;
        }

        #pragma unroll
        for (int r = 0; r < 4; ++r) {
            float fx, fy;
            asm("mov.b64 {%0,%1},%2;" : "=f"(fx), "=f"(fy) : "l"(acc[r]));
            float2* op = (float2*)&out[(size_t)(R0 + rq * 4 + r) * Hv + jc * 128 + 2 * jp];
            *op = make_float2(fx, fy);
        }
    }
}

// ---------------------------------------------------------------------------
// Phase 2: persistent scan, 4 independent batch groups of 32 CTAs.
// ---------------------------------------------------------------------------
__global__ void __launch_bounds__(NTHREADS, 1)
esn_scan_kernel(const float* __restrict__ W, float* __restrict__ out)
{
    extern __shared__ unsigned char smem_raw[];
    Smem& sm = *reinterpret_cast<Smem*>(smem_raw);

    const int tid  = threadIdx.x;
    const int lane = tid & 31;
    const int wid  = tid >> 5;
    const int jq   = lane & 7;          // j-quad
    const int bg   = lane >> 3;         // b-pair
    const int grp  = blockIdx.x & (NBG - 1);    // batch group / barrier group
    const int jg   = blockIdx.x >> 2;
    const int b0   = grp * BTILE;
    const int j0   = jg * JTILE;
    unsigned* bar  = &g_bar[grp * 64];

    // one-time W slice load: lanes along j -> conflict-free STS @ stride 32
    {
        const int jl = tid & 31;
        const int k0 = tid >> 5;        // 8 k-rows per iter
        for (int k = k0; k < Hv; k += 8) {
            sm.Ws[k * WS_STRIDE + jl] = W[(size_t)(j0 + jl) * Hv + k];
        }
    }

    const int hl_b  = tid & 7;
    const int hl_k4 = tid >> 3;

    const unsigned ws_s = (unsigned)__cvta_generic_to_shared(sm.Ws)
                          + (wid * KSLICE * WS_STRIDE + 4 * jq) * 4;
    const unsigned hd_s = (unsigned)__cvta_generic_to_shared(sm.hd)
                          + (wid * KSLICE * HD_STRIDE + 2 * bg) * 8;

    __syncthreads();

    const float lr  = 0.9f;
    const float olr = 1.0f - lr;

    for (int t = 0; t < Tv; ++t) {
        // prefetch u_in (independent of h; consumed after GEMM)
        const float u0 = out[((size_t)(b0 + wid) * Tv + t) * Hv + j0 + lane];

        float ssum  = 0.0f;
        float hprev = 0.0f;

        if (t > 0) {
            // group barrier: wait for all 32 CTAs of this batch group
            if (tid == 0) {
                const unsigned tgt = (unsigned)t * NJG;
                unsigned v;
                do {
                    asm volatile("ld.acquire.gpu.global.u32 %0, [%1];"
                                 : "=r"(v) : "l"(bar));
                } while (v < tgt);
            }
            __syncthreads();

            // gather h(t-1) tile -> SMEM, duplicated (v,v) pairs
            {
                const float4* hsrc = (const float4*)&h_buf[(t - 1) & 1][b0 + hl_b][0];
                #pragma unroll
                for (int i = 0; i < 8; ++i) {
                    int k4 = hl_k4 + 32 * i;
                    float4 v = __ldcg(hsrc + k4);
                    int k = k4 << 2;
                    sm.hd[(k + 0) * HD_STRIDE + hl_b] = make_float2(v.x, v.x);
                    sm.hd[(k + 1) * HD_STRIDE + hl_b] = make_float2(v.y, v.y);
                    sm.hd[(k + 2) * HD_STRIDE + hl_b] = make_float2(v.z, v.z);
                    sm.hd[(k + 3) * HD_STRIDE + hl_b] = make_float2(v.w, v.w);
                }
            }
            __syncthreads();

            // GEMM: per k = 1 LDS.128 (W quad) + 1 LDS.128 (dup h pair) + 4 FFMA2
            unsigned long long a0 = 0ull, a1 = 0ull, a2 = 0ull, a3 = 0ull;
            {
                unsigned wa = ws_s, ha = hd_s;
                #pragma unroll 16
                for (int k = 0; k < KSLICE; ++k) {
                    unsigned long long w01, w23, h00, h11;
                    asm("ld.shared.v2.u64 {%0,%1},[%2];"
                        : "=l"(w01), "=l"(w23) : "r"(wa));
                    asm("ld.shared.v2.u64 {%0,%1},[%2];"
                        : "=l"(h00), "=l"(h11) : "r"(ha));
                    asm("fma.rn.f32x2 %0,%1,%2,%0;" : "+l"(a0) : "l"(w01), "l"(h00));
                    asm("fma.rn.f32x2 %0,%1,%2,%0;" : "+l"(a1) : "l"(w23), "l"(h00));
                    asm("fma.rn.f32x2 %0,%1,%2,%0;" : "+l"(a2) : "l"(w01), "l"(h11));
                    asm("fma.rn.f32x2 %0,%1,%2,%0;" : "+l"(a3) : "l"(w23), "l"(h11));
                    wa += WS_STRIDE * 4;
                    ha += HD_STRIDE * 8;
                }
            }

            // k-split partials -> SMEM
            {
                float f0x, f0y, f1x, f1y, f2x, f2y, f3x, f3y;
                asm("mov.b64 {%0,%1},%2;" : "=f"(f0x), "=f"(f0y) : "l"(a0));
                asm("mov.b64 {%0,%1},%2;" : "=f"(f1x), "=f"(f1y) : "l"(a1));
                asm("mov.b64 {%0,%1},%2;" : "=f"(f2x), "=f"(f2y) : "l"(a2));
                asm("mov.b64 {%0,%1},%2;" : "=f"(f3x), "=f"(f3y) : "l"(a3));
                float* rp0 = &sm.red[wid][2 * bg][4 * jq];
                float* rp1 = &sm.red[wid][2 * bg + 1][4 * jq];
                *(float2*)(rp0)     = make_float2(f0x, f0y);
                *(float2*)(rp0 + 2) = make_float2(f1x, f1y);
                *(float2*)(rp1)     = make_float2(f2x, f2y);
                *(float2*)(rp1 + 2) = make_float2(f3x, f3y);
            }
            __syncthreads();

            #pragma unroll
            for (int w = 0; w < NWARPS; ++w)
                ssum += sm.red[w][wid][lane];

            hprev = sm.hd[(j0 + lane) * HD_STRIDE + wid].x;
        }

        // epilogue: h_new = 0.1*h + 0.9*tanh(u_in + h@W^T)
        const float u    = u0 + ssum;
        const float hnew = olr * hprev + lr * tanhf(u);

        h_buf[t & 1][b0 + wid][j0 + lane] = hnew;
        {
            float* op = &out[((size_t)(b0 + wid) * Tv + t) * Hv + j0 + lane];
            asm volatile("st.global.cs.f32 [%0], %1;" :: "l"(op), "f"(hnew));
        }

        __syncthreads();              // all stores of this CTA done
        if (tid == 0)                 // cumulative release: h_buf writes visible
            asm volatile("red.release.gpu.global.add.u32 [%0], 1;" :: "l"(bar));
    }
}

extern "C" void kernel_launch(void* const* d_in, const int* in_sizes, int n_in,
                              void* d_out, int out_size)
{
    const float* x   = (const float*)d_in[0];  // [32,1000,64]
    const float* Wiw = (const float*)d_in[1];  // [1024,64]
    const float* Wib = (const float*)d_in[2];  // [1024]
    const float* W   = (const float*)d_in[3];  // [1024,1024]
    float* out = (float*)d_out;                // [32,1000,1024]

    const size_t smem = sizeof(Smem);
    cudaFuncSetAttribute(esn_scan_kernel,
                         cudaFuncAttributeMaxDynamicSharedMemorySize, (int)smem);

    esn_uin_kernel<<<(Bv * Tv) / 16, 256>>>(x, Wiw, Wib, out);
    esn_scan_kernel<<<GRID, NTHREADS, smem>>>(W, out);
}

// round 5
// speedup vs baseline: 1.5052x; 1.5052x over previous
#include <cuda_runtime.h>

#define Bv 32
#define Tv 1000
#define DINv 64
#define Hv 1024

#define NBG 4
#define NJG 32
#define BTILE 8
#define JTILE 32
#define NTHREADS 256
#define GRID (NBG * NJG)     // 128 CTAs, 1/SM

#define WS 36                // W row stride (floats): 144B, 16B-aligned, conflict-free LDS.128
#define HS 10                // h row stride (floats): 40B, 8B-aligned for STS.64 gather
#define RS 274               // red k-slice stride (floats): odd-ish 16B phase for spread
#define NKS 64               // k-slices
#define KPT 16               // k per thread (strided by 64)

__device__ unsigned int g_bar[4 * 64];     // per-group counters, 256B apart
__device__ float h_buf[2][Bv][Hv];         // ping-pong h state

struct Smem {
    float Ws[Hv * WS];                     // 147456 B
    union {
        float h_s[Hv * HS];                // 40960 B  (live: gather -> end of GEMM)
        float red[NKS * RS];               // 70144 B  (live: after GEMM -> reduce read)
    } u;
};
// total = 217600 B < 227 KB

// ---------------------------------------------------------------------------
// Phase 1: u_in = x @ W_in^T + b -> out ; resets step counters.
// ---------------------------------------------------------------------------
__global__ void __launch_bounds__(256)
esn_uin_kernel(const float* __restrict__ x, const float* __restrict__ Wiw,
               const float* __restrict__ Wib, float* __restrict__ out)
{
    if (blockIdx.x == 0 && threadIdx.x < 4) g_bar[threadIdx.x * 64] = 0u;

    __shared__ float2 xs2[DINv * 18];
    __shared__ float  wis[DINv * 130];

    const int tid = threadIdx.x;
    const int R0  = blockIdx.x * 16;

    {
        const int kk = tid & 63, r4 = tid >> 6;
        #pragma unroll
        for (int i = 0; i < 4; ++i) {
            int r = r4 * 4 + i;
            float v = x[(size_t)(R0 + r) * DINv + kk];
            xs2[kk * 18 + r] = make_float2(v, v);
        }
    }

    const int jp = tid & 63;
    const int rq = tid >> 6;
    const unsigned wis_s = (unsigned)__cvta_generic_to_shared(wis);
    const unsigned xs_s  = (unsigned)__cvta_generic_to_shared(xs2);

    for (int jc = 0; jc < 8; ++jc) {
        __syncthreads();
        for (int idx = tid; idx < 128 * DINv; idx += 256) {
            int jj = idx >> 6, kk = idx & 63;
            wis[kk * 130 + jj] = Wiw[(jc * 128 + jj) * DINv + kk];
        }
        __syncthreads();

        float2 bias2 = *(const float2*)&Wib[jc * 128 + 2 * jp];
        unsigned long long acc[4], b2;
        asm("mov.b64 %0,{%1,%2};" : "=l"(b2) : "f"(bias2.x), "f"(bias2.y));
        #pragma unroll
        for (int r = 0; r < 4; ++r) acc[r] = b2;

        unsigned wa = wis_s + (2 * jp) * 4;
        unsigned xa = xs_s + (rq * 4) * 8;
        #pragma unroll 8
        for (int k = 0; k < DINv; ++k) {
            unsigned long long w01, x0, x1, x2, x3;
            asm("ld.shared.u64 %0,[%1];" : "=l"(w01) : "r"(wa));
            asm("ld.shared.u64 %0,[%1];" : "=l"(x0) : "r"(xa));
            asm("ld.shared.u64 %0,[%1+8];" : "=l"(x1) : "r"(xa));
            asm("ld.shared.u64 %0,[%1+16];" : "=l"(x2) : "r"(xa));
            asm("ld.shared.u64 %0,[%1+24];" : "=l"(x3) : "r"(xa));
            asm("fma.rn.f32x2 %0,%1,%2,%0;" : "+l"(acc[0]) : "l"(w01), "l"(x0));
            asm("fma.rn.f32x2 %0,%1,%2,%0;" : "+l"(acc[1]) : "l"(w01), "l"(x1));
            asm("fma.rn.f32x2 %0,%1,%2,%0;" : "+l"(acc[2]) : "l"(w01), "l"(x2));
            asm("fma.rn.f32x2 %0,%1,%2,%0;" : "+l"(acc[3]) : "l"(w01), "l"(x3));
            wa += 130 * 4;
            xa += 18 * 8;
        }

        #pragma unroll
        for (int r = 0; r < 4; ++r) {
            float fx, fy;
            asm("mov.b64 {%0,%1},%2;" : "=f"(fx), "=f"(fy) : "l"(acc[r]));
            float2* op = (float2*)&out[(size_t)(R0 + rq * 4 + r) * Hv + jc * 128 + 2 * jp];
            *op = make_float2(fx, fy);
        }
    }
}

// ---------------------------------------------------------------------------
// Phase 2: persistent scan. Thread = 8j x 8b register block over 16 strided k.
// ---------------------------------------------------------------------------
__global__ void __launch_bounds__(NTHREADS, 1)
esn_scan_kernel(const float* __restrict__ W, float* __restrict__ out)
{
    extern __shared__ unsigned char smem_raw[];
    Smem& sm = *reinterpret_cast<Smem*>(smem_raw);

    const int tid  = threadIdx.x;
    const int lane = tid & 31;
    const int wid  = tid >> 5;
    const int jt   = tid & 3;           // j-octet: j = jt*8 .. jt*8+7
    const int ks   = tid >> 2;          // k-slice 0..63 (k = ks + 64*i)
    const int grp  = blockIdx.x & (NBG - 1);
    const int jg   = blockIdx.x >> 2;
    const int b0   = grp * BTILE;
    const int j0   = jg * JTILE;
    unsigned* bar  = &g_bar[grp * 64];

    // one-time W slice: Ws[k*36 + jl] = W[j0+jl][k]  (conflict-free STS)
    {
        const int jl = tid & 31;
        for (int k4 = tid >> 5; k4 < Hv / 4; k4 += 8) {
            float4 v = *(const float4*)&W[(size_t)(j0 + jl) * Hv + k4 * 4];
            sm.Ws[(k4 * 4 + 0) * WS + jl] = v.x;
            sm.Ws[(k4 * 4 + 1) * WS + jl] = v.y;
            sm.Ws[(k4 * 4 + 2) * WS + jl] = v.z;
            sm.Ws[(k4 * 4 + 3) * WS + jl] = v.w;
        }
    }

    // gather mapping: thread stages b-pair (hb2, hb2+1) for 16 k's over 4 iters
    const int hb2 = (tid & 3) * 2;
    const int hk4 = tid >> 2;           // 0..63

    const unsigned ws_s = (unsigned)__cvta_generic_to_shared(sm.Ws)
                          + (ks * WS + jt * 8) * 4;
    const unsigned hs_s = (unsigned)__cvta_generic_to_shared(sm.u.h_s)
                          + (ks * HS) * 4;

    __syncthreads();

    const float lr  = 0.9f;
    const float olr = 1.0f - lr;

    for (int t = 0; t < Tv; ++t) {
        // prefetch u_in (independent of h)
        const float u0 = out[((size_t)(b0 + wid) * Tv + t) * Hv + j0 + lane];

        float ssum  = 0.0f;
        float hprev = 0.0f;

        if (t > 0) {
            // group barrier
            if (tid == 0) {
                const unsigned tgt = (unsigned)t * NJG;
                unsigned v;
                do {
                    asm volatile("ld.acquire.gpu.global.u32 %0, [%1];"
                                 : "=r"(v) : "l"(bar));
                } while (v < tgt);
            }
            __syncthreads();

            // gather h(t-1)[b0..b0+7][:] -> h_s[k][b] (STS.64 over b-pairs)
            {
                const int tp = (t - 1) & 1;
                const float4* pa = (const float4*)&h_buf[tp][b0 + hb2][0];
                const float4* pb = (const float4*)&h_buf[tp][b0 + hb2 + 1][0];
                #pragma unroll
                for (int i = 0; i < 4; ++i) {
                    int k4 = hk4 + 64 * i;
                    float4 va = __ldcg(pa + k4);
                    float4 vb = __ldcg(pb + k4);
                    int k = k4 << 2;
                    *(float2*)&sm.u.h_s[(k + 0) * HS + hb2] = make_float2(va.x, vb.x);
                    *(float2*)&sm.u.h_s[(k + 1) * HS + hb2] = make_float2(va.y, vb.y);
                    *(float2*)&sm.u.h_s[(k + 2) * HS + hb2] = make_float2(va.z, vb.z);
                    *(float2*)&sm.u.h_s[(k + 3) * HS + hb2] = make_float2(va.w, vb.w);
                }
            }
            __syncthreads();

            // hprev must be read before red[] (aliases h_s) is written
            hprev = sm.u.h_s[(j0 + lane) * HS + wid];

            // GEMM: per k = 2 LDS.128 (8 W, j-pairs) + 8 LDS.32 (h bcast)
            //       + 8 dup movs + 32 FFMA2   -> 16 wf/k/warp
            unsigned long long a[4][8];
            #pragma unroll
            for (int q = 0; q < 4; ++q)
                #pragma unroll
                for (int b = 0; b < 8; ++b) a[q][b] = 0ull;

            {
                unsigned wa = ws_s, ha = hs_s;
                #pragma unroll
                for (int i = 0; i < KPT; ++i) {
                    unsigned long long w01, w23, w45, w67;
                    asm("ld.shared.v2.u64 {%0,%1},[%2];"
                        : "=l"(w01), "=l"(w23) : "r"(wa));
                    asm("ld.shared.v2.u64 {%0,%1},[%2+16];"
                        : "=l"(w45), "=l"(w67) : "r"(wa));
                    #pragma unroll
                    for (int b = 0; b < 8; ++b) {
                        float hv;
                        unsigned long long hd;
                        asm("ld.shared.f32 %0,[%1];" : "=f"(hv) : "r"(ha + b * 4));
                        asm("mov.b64 %0,{%1,%1};" : "=l"(hd) : "f"(hv));
                        asm("fma.rn.f32x2 %0,%1,%2,%0;" : "+l"(a[0][b]) : "l"(w01), "l"(hd));
                        asm("fma.rn.f32x2 %0,%1,%2,%0;" : "+l"(a[1][b]) : "l"(w23), "l"(hd));
                        asm("fma.rn.f32x2 %0,%1,%2,%0;" : "+l"(a[2][b]) : "l"(w45), "l"(hd));
                        asm("fma.rn.f32x2 %0,%1,%2,%0;" : "+l"(a[3][b]) : "l"(w67), "l"(hd));
                    }
                    wa += 64 * WS * 4;
                    ha += 64 * HS * 4;
                }
            }

            __syncthreads();   // all h_s reads done before red overwrite

            // write k-slice partials: red[ks][b][j] (float2 over j-pairs)
            #pragma unroll
            for (int b = 0; b < 8; ++b) {
                #pragma unroll
                for (int q = 0; q < 4; ++q) {
                    float fx, fy;
                    asm("mov.b64 {%0,%1},%2;" : "=f"(fx), "=f"(fy) : "l"(a[q][b]));
                    *(float2*)&sm.u.red[ks * RS + b * 34 + jt * 8 + q * 2] =
                        make_float2(fx, fy);
                }
            }
            __syncthreads();

            // reduce 64 k-slices for output (b=wid, j=lane)
            {
                const float* rp = &sm.u.red[wid * 34 + lane];
                #pragma unroll 16
                for (int s = 0; s < NKS; ++s) ssum += rp[s * RS];
            }
        }

        // epilogue
        const float u    = u0 + ssum;
        const float hnew = olr * hprev + lr * tanhf(u);

        h_buf[t & 1][b0 + wid][j0 + lane] = hnew;
        out[((size_t)(b0 + wid) * Tv + t) * Hv + j0 + lane] = hnew;

        __syncthreads();     // CTA stores + red reads done
        if (tid == 0)
            asm volatile("red.release.gpu.global.add.u32 [%0], 1;" :: "l"(bar));
    }
}

extern "C" void kernel_launch(void* const* d_in, const int* in_sizes, int n_in,
                              void* d_out, int out_size)
{
    const float* x   = (const float*)d_in[0];  // [32,1000,64]
    const float* Wiw = (const float*)d_in[1];  // [1024,64]
    const float* Wib = (const float*)d_in[2];  // [1024]
    const float* W   = (const float*)d_in[3];  // [1024,1024]
    float* out = (float*)d_out;                // [32,1000,1024]

    const size_t smem = sizeof(Smem);
    cudaFuncSetAttribute(esn_scan_kernel,
                         cudaFuncAttributeMaxDynamicSharedMemorySize, (int)smem);

    esn_uin_kernel<<<(Bv * Tv) / 16, 256>>>(x, Wiw, Wib, out);
    esn_scan_kernel<<<GRID, NTHREADS, smem>>>(W, out);
}